// round 14
// baseline (speedup 1.0000x reference)
#include <cuda_runtime.h>
#include <cuda_bf16.h>
#include <cuda_fp16.h>
#include <math.h>
#include <stdint.h>

// Problem constants
#define BB   4
#define TT   512
#define HH   2048
#define VV   32000
#define BT   (BB*TT)          // 2048 rows
#define NCTAY 500
#define CANDP 512             // padded stride for candidate table
#define BETA_C   0.1f
#define EPS_LO_C 0.2f
#define EPS_HI_C 0.2f

// GEMM tiling (legacy mma.sync path; tcgen05 not available on this target)
#define BM 128
#define BN 64                  // narrow CTA -> 4 CTAs/SM, 4 barrier domains
#define KC 64                  // K chunk in fp16 elems
#define NKS (KC/16)            // 4 ks-steps per chunk
#define NCHUNK (HH/KC)         // 32
#define NST 2                  // 2-stage: empirical optimum
#define PITCH 144              // 128B data + 16B pad; conflict-free for LDSM
#define A_OFF  0
#define BH_OFF 18432           // 128 rows * 144
#define STAGE_BYTES 27648      // + 64 rows * 144
#define SMEM_DYN (NST*STAGE_BYTES)   // 55296 -> 4 CTAs/SM
#define GT 128                 // threads per CTA

// ---------------- scratch (static device globals; no allocations) ----------------
__device__ float              g_sum_pol[BT];
__device__ float              g_sum_ref[BT];
__device__ unsigned long long g_cand[BT*CANDP];   // per (row, ctaY) noisy max
__device__ uint4              g_top[BT];          // top-3 candidate cols per row (w unused)
__device__ float              g_pdot[BT];
__device__ float              g_rdot[BT];
__device__ __align__(1024) __half g_xh [BT*HH];
__device__ __align__(1024) __half g_wh [(size_t)VV*HH];
__device__ __align__(1024) __half g_rxh[BT*HH];
__device__ __align__(1024) __half g_rwh[(size_t)VV*HH];

// ---------------- PTX helpers ----------------
__device__ __forceinline__ uint32_t s2u(const void* p) {
    uint32_t a;
    asm("{ .reg .u64 t; cvta.to.shared.u64 t, %1; cvt.u32.u64 %0, t; }" : "=r"(a) : "l"(p));
    return a;
}
__device__ __forceinline__ void cpasync16(uint32_t s, const void* g) {
    asm volatile("cp.async.cg.shared.global [%0], [%1], 16;" :: "r"(s), "l"(g) : "memory");
}
__device__ __forceinline__ void cp_commit() {
    asm volatile("cp.async.commit_group;" ::: "memory");
}
template <int N>
__device__ __forceinline__ void cp_wait() {
    asm volatile("cp.async.wait_group %0;" :: "n"(N) : "memory");
}
__device__ __forceinline__ void ldsm4(uint32_t* r, uint32_t a) {
    asm volatile("ldmatrix.sync.aligned.m8n8.x4.shared.b16 {%0,%1,%2,%3}, [%4];"
                 : "=r"(r[0]), "=r"(r[1]), "=r"(r[2]), "=r"(r[3]) : "r"(a));
}
__device__ __forceinline__ void mma16816(float* d, const uint32_t* a, const uint32_t* b) {
    asm volatile(
        "mma.sync.aligned.m16n8k16.row.col.f32.f16.f16.f32 "
        "{%0,%1,%2,%3}, {%4,%5,%6,%7}, {%8,%9}, {%0,%1,%2,%3};"
        : "+f"(d[0]), "+f"(d[1]), "+f"(d[2]), "+f"(d[3])
        : "r"(a[0]), "r"(a[1]), "r"(a[2]), "r"(a[3]), "r"(b[0]), "r"(b[1]));
}
__device__ __forceinline__ unsigned fkey(float f) {
    unsigned u = __float_as_uint(f);
    return (u & 0x80000000u) ? ~u : (u | 0x80000000u);
}
// FMA-only exp
__device__ __forceinline__ float fexp(float x) {
    float t = x * 1.4426950408889634f;
    float r = rintf(t);
    float u = (t - r) * 0.6931471805599453f;
    float p = 8.3333333e-3f;
    p = fmaf(p, u, 4.1666667e-2f);
    p = fmaf(p, u, 1.6666667e-1f);
    p = fmaf(p, u, 0.5f);
    p = fmaf(p, u, 1.0f);
    p = fmaf(p, u, 1.0f);
    int e = (int)r;
    return p * __int_as_float((e + 127) << 23);
}

// ---------------- fused convert + init: all 4 tensors fp32->fp16 ----------------
#define NXI (BT*HH/8)                       // 524288 items per activation tensor
#define NWI ((int)((size_t)VV*HH/8))        // 8192000 items per weight tensor
#define NTOT (2*NXI + 2*NWI)                // 17432576

__global__ void convert_all(const float* __restrict__ x,  const float* __restrict__ rx,
                            const float* __restrict__ w,  const float* __restrict__ rw,
                            __half* __restrict__ xh, __half* __restrict__ rxh,
                            __half* __restrict__ wh, __half* __restrict__ rwh) {
    int i = blockIdx.x * blockDim.x + threadIdx.x;
    // fold init of the stats/candidate scratch into this launch
    if (i < BT) { g_sum_pol[i] = 0.0f; g_sum_ref[i] = 0.0f; }
    if (i < BT * CANDP) g_cand[i] = 0ull;
    if (i >= NTOT) return;
    const float* src;
    __half* dst;
    int j;
    if (i < NXI)            { src = x;  dst = xh;  j = i; }
    else if (i < 2*NXI)     { src = rx; dst = rxh; j = i - NXI; }
    else if (i < 2*NXI+NWI) { src = w;  dst = wh;  j = i - 2*NXI; }
    else                    { src = rw; dst = rwh; j = i - 2*NXI - NWI; }

    float4 v0 = ((const float4*)src)[2*(size_t)j];
    float4 v1 = ((const float4*)src)[2*(size_t)j+1];
    __half2 h[4];
    h[0] = __floats2half2_rn(v0.x, v0.y);
    h[1] = __floats2half2_rn(v0.z, v0.w);
    h[2] = __floats2half2_rn(v1.x, v1.y);
    h[3] = __floats2half2_rn(v1.z, v1.w);
    ((uint4*)dst)[(size_t)j] = *(uint4*)h;
}

// ---------------- single-fp16 tensor-core GEMM + fused softmax-stats ----------------
// blockIdx.z = 0: policy (argmax candidates on), 1: reference
__global__ void __launch_bounds__(GT, 4)
gemm_mma(const __half* __restrict__ pAh, const __half* __restrict__ pBh,
         const __half* __restrict__ rAh, const __half* __restrict__ rBh,
         float* __restrict__ sum_pol, float* __restrict__ sum_ref,
         unsigned long long* __restrict__ cand) {
    extern __shared__ char smem[];
    const uint32_t sb = s2u(smem);
    const int tid  = threadIdx.x;
    const int lane = tid & 31;
    const int wid  = tid >> 5;         // 0..3
    const int wm   = wid >> 1;          // 0..1 (64-row slab)
    const int wn   = wid & 1;           // 0..1 (32-col slab)
    const int m0 = blockIdx.x * BM;
    const int n0 = blockIdx.y * BN;
    const int zz = blockIdx.z;          // 0 = policy, 1 = reference

    const __half* Ah = zz ? rAh : pAh;
    const __half* Bh = zz ? rBh : pBh;
    float* sumexp = zz ? sum_ref : sum_pol;
    const int do_max = (zz == 0);

    float acc[4][4][4];
#pragma unroll
    for (int mt = 0; mt < 4; ++mt)
#pragma unroll
        for (int nt = 0; nt < 4; ++nt)
#pragma unroll
            for (int j = 0; j < 4; ++j) acc[mt][nt][j] = 0.0f;

    // cp.async per stage: A 128 rows x 8 chunks = 1024, B 64 x 8 = 512 -> 12/thread
    auto load_stage = [&](int st, int k0) {
        uint32_t stb = sb + st * STAGE_BYTES;
#pragma unroll
        for (int it = 0; it < 8; ++it) {           // A chunks: ids 0..1023
            int id  = tid + it * GT;
            int row = id >> 3;
            int cq  = id & 7;
            uint32_t so = (uint32_t)row * PITCH + (uint32_t)cq * 16;
            cpasync16(stb + A_OFF + so, Ah + (size_t)(m0 + row) * HH + k0 + cq * 8);
        }
#pragma unroll
        for (int it = 0; it < 4; ++it) {           // B chunks: ids 0..511
            int id  = tid + it * GT;
            int row = id >> 3;
            int cq  = id & 7;
            uint32_t so = (uint32_t)row * PITCH + (uint32_t)cq * 16;
            cpasync16(stb + BH_OFF + so, Bh + (size_t)(n0 + row) * HH + k0 + cq * 8);
        }
    };

    load_stage(0, 0);
    cp_commit();

    const int arow_base = wm * 64 + (lane & 15);
    const int a_half    = (lane >> 4);
    const int brow_base = wn * 32 + ((lane >> 4) & 1) * 8 + (lane & 7);
    const int bksel     = (lane >> 3) & 1;

    for (int c = 0; c < NCHUNK; ++c) {
        if (c + 1 < NCHUNK) load_stage((c + 1) & 1, (c + 1) * KC);
        cp_commit();
        cp_wait<1>();
        __syncthreads();

        uint32_t stb = sb + (c & 1) * STAGE_BYTES;
#pragma unroll
        for (int ks = 0; ks < NKS; ++ks) {
            uint32_t acol = (ks * 2 + a_half) * 16;
            uint32_t bcol = (ks * 2 + bksel) * 16;
            uint32_t ah[4][4], bh[2][4];
#pragma unroll
            for (int mt = 0; mt < 4; ++mt)
                ldsm4(ah[mt], stb + A_OFF + (uint32_t)(arow_base + mt * 16) * PITCH + acol);
#pragma unroll
            for (int p = 0; p < 2; ++p)
                ldsm4(bh[p], stb + BH_OFF + (uint32_t)(brow_base + p * 16) * PITCH + bcol);
#pragma unroll
            for (int mt = 0; mt < 4; ++mt)
#pragma unroll
                for (int nt = 0; nt < 4; ++nt)
                    mma16816(acc[mt][nt], ah[mt], &bh[nt >> 1][(nt & 1) * 2]);
        }
        __syncthreads();
    }

    // ---- epilogue: row-wise sum(exp); policy also records CTA-local row max ----
#pragma unroll
    for (int mt = 0; mt < 4; ++mt) {
#pragma unroll
        for (int half = 0; half < 2; ++half) {
            int row = m0 + wm * 64 + mt * 16 + (lane >> 2) + half * 8;
            float s = 0.0f;
            float vmax = -3.402823466e+38f;
            unsigned am = 0;
#pragma unroll
            for (int nt = 0; nt < 4; ++nt)
#pragma unroll
                for (int j = 0; j < 2; ++j) {
                    float v = acc[mt][nt][half * 2 + j];
                    s += fexp(v);
                    unsigned col = (unsigned)(n0 + wn * 32 + nt * 8 + (lane & 3) * 2 + j);
                    if (v > vmax) { vmax = v; am = col; }
                }
#pragma unroll
            for (int m = 1; m < 4; m <<= 1) {
                s += __shfl_xor_sync(0xFFFFFFFFu, s, m);
                float ov = __shfl_xor_sync(0xFFFFFFFFu, vmax, m);
                unsigned oa = __shfl_xor_sync(0xFFFFFFFFu, am, m);
                if (ov > vmax || (ov == vmax && oa < am)) { vmax = ov; am = oa; }
            }
            if ((lane & 3) == 0) {
                atomicAdd(&sumexp[row], s);
                if (do_max) {
                    unsigned long long p = ((unsigned long long)fkey(vmax) << 32)
                                         | (unsigned long long)(0xFFFFFFFFu - am);
                    atomicMax(&cand[(size_t)row * CANDP + blockIdx.y], p);
                }
            }
        }
    }
}

// ---------------- global top-3 candidates per row ----------------
__global__ void top3_kernel() {
    __shared__ unsigned long long sv[512];
    int row = blockIdx.x;
    int tid = threadIdx.x;
    unsigned long long v = (tid < NCTAY) ? g_cand[(size_t)row * CANDP + tid] : 0ull;
    sv[tid] = v; __syncthreads();
    for (int s = 256; s > 0; s >>= 1) {
        if (tid < s) sv[tid] = (sv[tid] > sv[tid + s]) ? sv[tid] : sv[tid + s];
        __syncthreads();
    }
    unsigned long long m1 = sv[0];
    __syncthreads();
    sv[tid] = (v == m1) ? 0ull : v; __syncthreads();
    for (int s = 256; s > 0; s >>= 1) {
        if (tid < s) sv[tid] = (sv[tid] > sv[tid + s]) ? sv[tid] : sv[tid + s];
        __syncthreads();
    }
    unsigned long long m2 = sv[0];
    __syncthreads();
    sv[tid] = (v == m1 || v == m2) ? 0ull : v; __syncthreads();
    for (int s = 256; s > 0; s >>= 1) {
        if (tid < s) sv[tid] = (sv[tid] > sv[tid + s]) ? sv[tid] : sv[tid + s];
        __syncthreads();
    }
    if (tid == 0) {
        unsigned long long m3 = sv[0];
        unsigned c1 = 0xFFFFFFFFu - (unsigned)(m1 & 0xFFFFFFFFull);
        unsigned c2 = (m2 != 0ull) ? (0xFFFFFFFFu - (unsigned)(m2 & 0xFFFFFFFFull)) : c1;
        unsigned c3 = (m3 != 0ull) ? (0xFFFFFFFFu - (unsigned)(m3 & 0xFFFFFFFFull)) : c1;
        g_top[row] = make_uint4(c1, c2, c3, 0u);
    }
}

// ---------------- exact fp32 dots for top-3, pick true argmax ----------------
__global__ void gather_pick(const float* __restrict__ x, const float* __restrict__ w,
                            const float* __restrict__ rx, const float* __restrict__ rw) {
    __shared__ float sd[6];
    int row = blockIdx.x;
    int tid = threadIdx.x;
    int wrp = tid >> 5;         // 0..5: (model, cand) = (wrp/3, wrp%3)
    int lane = tid & 31;
    uint4 t = g_top[row];
    unsigned cols[3] = { t.x, t.y, t.z };
    unsigned col = cols[wrp % 3];
    const float* a = (wrp < 3) ? (x + (size_t)row * HH) : (rx + (size_t)row * HH);
    const float* b = (wrp < 3) ? (w + (size_t)col * HH) : (rw + (size_t)col * HH);
    float s = 0.0f;
    for (int h = lane; h < HH; h += 32) s = fmaf(a[h], b[h], s);
#pragma unroll
    for (int m = 16; m >= 1; m >>= 1) s += __shfl_xor_sync(0xFFFFFFFFu, s, m);
    if (lane == 0) sd[wrp] = s;
    __syncthreads();
    if (tid == 0) {
        int best = 0;
        for (int k = 1; k < 3; ++k) {
            if (sd[k] > sd[best] || (sd[k] == sd[best] && cols[k] < cols[best])) best = k;
        }
        g_pdot[row] = sd[best];
        g_rdot[row] = sd[3 + best];
    }
}

// ---------------- final scalar loss ----------------
__global__ void loss_kernel(const float* __restrict__ adv,
                            const float* __restrict__ oldlp,
                            const int*   __restrict__ mask,
                            float* __restrict__ out) {
    __shared__ float sl[256], sm[256];
    int tid = threadIdx.x;
    float accl = 0.0f, accm = 0.0f;
    for (int r = tid; r < BT; r += 256) {
        int b = r / TT;
        float lse_p = logf(g_sum_pol[r]);
        float lse_r = logf(g_sum_ref[r]);
        float chosen_lp = g_pdot[r] - lse_p;
        float ref_lp    = g_rdot[r] - lse_r;

        float c1 = expf(chosen_lp - oldlp[r]);
        float c2 = fminf(fmaxf(c1, 1.0f - EPS_LO_C), 1.0f + EPS_HI_C);
        float a  = adv[b];
        float ptl = -fminf(c1 * a, c2 * a);

        float delta = ref_lp - chosen_lp;
        float kl = expf(delta) - delta - 1.0f;
        ptl += BETA_C * kl;

        float m = (float)mask[r];
        accl += ptl * m;
        accm += m;
    }
    sl[tid] = accl; sm[tid] = accm;
    __syncthreads();
    for (int s = 128; s > 0; s >>= 1) {
        if (tid < s) { sl[tid] += sl[tid + s]; sm[tid] += sm[tid + s]; }
        __syncthreads();
    }
    if (tid == 0) out[0] = sl[0] / fmaxf(sm[0], 1.0f);
}

// ---------------- launch ----------------
extern "C" void kernel_launch(void* const* d_in, const int* in_sizes, int n_in,
                              void* d_out, int out_size) {
    const float* x    = (const float*)d_in[0];
    const float* w    = (const float*)d_in[1];
    const float* rx   = (const float*)d_in[2];
    const float* rw   = (const float*)d_in[3];
    const float* adv  = (const float*)d_in[4];
    const float* oldl = (const float*)d_in[5];
    const int*   msk  = (const int*)d_in[6];
    float* out = (float*)d_out;

    float *sum_pol, *sum_ref;
    unsigned long long* cand;
    __half *xh, *wh, *rxh, *rwh;
    cudaGetSymbolAddress((void**)&sum_pol, g_sum_pol);
    cudaGetSymbolAddress((void**)&sum_ref, g_sum_ref);
    cudaGetSymbolAddress((void**)&cand,    g_cand);
    cudaGetSymbolAddress((void**)&xh,  g_xh);
    cudaGetSymbolAddress((void**)&wh,  g_wh);
    cudaGetSymbolAddress((void**)&rxh, g_rxh);
    cudaGetSymbolAddress((void**)&rwh, g_rwh);

    cudaFuncSetAttribute(gemm_mma, cudaFuncAttributeMaxDynamicSharedMemorySize, SMEM_DYN);

    convert_all<<<(NTOT + 255) / 256, 256>>>(x, rx, w, rw, xh, rxh, wh, rwh);

    dim3 grid(BT / BM, VV / BN, 2);   // (16, 500, 2): z = pol/ref
    gemm_mma<<<grid, GT, SMEM_DYN>>>(xh, wh, rxh, rwh, sum_pol, sum_ref, cand);

    top3_kernel<<<BT, 512>>>();
    gather_pick<<<BT, 192>>>(x, w, rx, rw);
    loss_kernel<<<1, 256>>>(adv, oldl, msk, out);
}

// round 15
// speedup vs baseline: 1.0326x; 1.0326x over previous
#include <cuda_runtime.h>
#include <cuda_bf16.h>
#include <cuda_fp16.h>
#include <math.h>
#include <stdint.h>

// Problem constants
#define BB   4
#define TT   512
#define HH   2048
#define VV   32000
#define BT   (BB*TT)          // 2048 rows
#define NCTAY 500
#define CANDP 512             // padded stride for candidate table
#define BETA_C   0.1f
#define EPS_LO_C 0.2f
#define EPS_HI_C 0.2f

// GEMM tiling (legacy mma.sync path; tcgen05 not available on this target)
#define BM 128
#define BN 64                  // narrow CTA -> 4 CTAs/SM, 4 barrier domains
#define KC 64                  // K chunk in fp16 elems
#define NKS (KC/16)            // 4 ks-steps per chunk
#define NCHUNK (HH/KC)         // 32
#define NST 2                  // 2-stage: empirical optimum
#define PITCH 144              // 128B data + 16B pad; conflict-free for LDSM
#define A_OFF  0
#define BH_OFF 18432           // 128 rows * 144
#define STAGE_BYTES 27648      // + 64 rows * 144
#define SMEM_DYN (NST*STAGE_BYTES)   // 55296 -> 4 CTAs/SM
#define GT 128                 // threads per CTA

// ---------------- scratch (static device globals; no allocations) ----------------
__device__ float              g_sum_pol[BT];
__device__ float              g_sum_ref[BT];
__device__ unsigned long long g_cand[BT*CANDP];   // per (row, ctaY) noisy max
__device__ float              g_pdot[BT];
__device__ float              g_rdot[BT];
__device__ __align__(1024) __half g_xh [BT*HH];
__device__ __align__(1024) __half g_wh [(size_t)VV*HH];
__device__ __align__(1024) __half g_rxh[BT*HH];
__device__ __align__(1024) __half g_rwh[(size_t)VV*HH];

// ---------------- PTX helpers ----------------
__device__ __forceinline__ uint32_t s2u(const void* p) {
    uint32_t a;
    asm("{ .reg .u64 t; cvta.to.shared.u64 t, %1; cvt.u32.u64 %0, t; }" : "=r"(a) : "l"(p));
    return a;
}
__device__ __forceinline__ void cpasync16(uint32_t s, const void* g) {
    asm volatile("cp.async.cg.shared.global [%0], [%1], 16;" :: "r"(s), "l"(g) : "memory");
}
__device__ __forceinline__ void cp_commit() {
    asm volatile("cp.async.commit_group;" ::: "memory");
}
template <int N>
__device__ __forceinline__ void cp_wait() {
    asm volatile("cp.async.wait_group %0;" :: "n"(N) : "memory");
}
__device__ __forceinline__ void ldsm4(uint32_t* r, uint32_t a) {
    asm volatile("ldmatrix.sync.aligned.m8n8.x4.shared.b16 {%0,%1,%2,%3}, [%4];"
                 : "=r"(r[0]), "=r"(r[1]), "=r"(r[2]), "=r"(r[3]) : "r"(a));
}
__device__ __forceinline__ void mma16816(float* d, const uint32_t* a, const uint32_t* b) {
    asm volatile(
        "mma.sync.aligned.m16n8k16.row.col.f32.f16.f16.f32 "
        "{%0,%1,%2,%3}, {%4,%5,%6,%7}, {%8,%9}, {%0,%1,%2,%3};"
        : "+f"(d[0]), "+f"(d[1]), "+f"(d[2]), "+f"(d[3])
        : "r"(a[0]), "r"(a[1]), "r"(a[2]), "r"(a[3]), "r"(b[0]), "r"(b[1]));
}
__device__ __forceinline__ unsigned fkey(float f) {
    unsigned u = __float_as_uint(f);
    return (u & 0x80000000u) ? ~u : (u | 0x80000000u);
}
// FMA-only exp
__device__ __forceinline__ float fexp(float x) {
    float t = x * 1.4426950408889634f;
    float r = rintf(t);
    float u = (t - r) * 0.6931471805599453f;
    float p = 8.3333333e-3f;
    p = fmaf(p, u, 4.1666667e-2f);
    p = fmaf(p, u, 1.6666667e-1f);
    p = fmaf(p, u, 0.5f);
    p = fmaf(p, u, 1.0f);
    p = fmaf(p, u, 1.0f);
    int e = (int)r;
    return p * __int_as_float((e + 127) << 23);
}

// ---------------- init ----------------
__global__ void init_kernel() {
    int i = blockIdx.x * blockDim.x + threadIdx.x;
    if (i < BT) { g_sum_pol[i] = 0.0f; g_sum_ref[i] = 0.0f; }
    if (i < BT * CANDP) g_cand[i] = 0ull;
}

// ---------------- fused convert: all 4 tensors, fp32 -> fp16, 8 elems/item ----------------
#define NXI (BT*HH/8)                       // 524288 items per activation tensor
#define NWI ((int)((size_t)VV*HH/8))        // 8192000 items per weight tensor
#define NTOT (2*NXI + 2*NWI)                // 17432576

__global__ void convert_all(const float* __restrict__ x,  const float* __restrict__ rx,
                            const float* __restrict__ w,  const float* __restrict__ rw,
                            __half* __restrict__ xh, __half* __restrict__ rxh,
                            __half* __restrict__ wh, __half* __restrict__ rwh) {
    int i = blockIdx.x * blockDim.x + threadIdx.x;
    if (i >= NTOT) return;
    const float* src;
    __half* dst;
    int j;
    if (i < NXI)            { src = x;  dst = xh;  j = i; }
    else if (i < 2*NXI)     { src = rx; dst = rxh; j = i - NXI; }
    else if (i < 2*NXI+NWI) { src = w;  dst = wh;  j = i - 2*NXI; }
    else                    { src = rw; dst = rwh; j = i - 2*NXI - NWI; }

    float4 v0 = ((const float4*)src)[2*(size_t)j];
    float4 v1 = ((const float4*)src)[2*(size_t)j+1];
    __half2 h[4];
    h[0] = __floats2half2_rn(v0.x, v0.y);
    h[1] = __floats2half2_rn(v0.z, v0.w);
    h[2] = __floats2half2_rn(v1.x, v1.y);
    h[3] = __floats2half2_rn(v1.z, v1.w);
    ((uint4*)dst)[(size_t)j] = *(uint4*)h;
}

// ---------------- single-fp16 tensor-core GEMM + fused softmax-stats ----------------
__global__ void __launch_bounds__(GT, 4)
gemm_mma(const __half* __restrict__ Ah, const __half* __restrict__ Bh,
         float* __restrict__ sumexp, unsigned long long* __restrict__ cand,
         int do_max) {
    extern __shared__ char smem[];
    const uint32_t sb = s2u(smem);
    const int tid  = threadIdx.x;
    const int lane = tid & 31;
    const int wid  = tid >> 5;         // 0..3
    const int wm   = wid >> 1;          // 0..1 (64-row slab)
    const int wn   = wid & 1;           // 0..1 (32-col slab)
    const int m0 = blockIdx.x * BM;
    const int n0 = blockIdx.y * BN;

    float acc[4][4][4];
#pragma unroll
    for (int mt = 0; mt < 4; ++mt)
#pragma unroll
        for (int nt = 0; nt < 4; ++nt)
#pragma unroll
            for (int j = 0; j < 4; ++j) acc[mt][nt][j] = 0.0f;

    // cp.async per stage: A 128 rows x 8 chunks = 1024, B 64 x 8 = 512 -> 12/thread
    auto load_stage = [&](int st, int k0) {
        uint32_t stb = sb + st * STAGE_BYTES;
#pragma unroll
        for (int it = 0; it < 8; ++it) {           // A chunks: ids 0..1023
            int id  = tid + it * GT;
            int row = id >> 3;
            int cq  = id & 7;
            uint32_t so = (uint32_t)row * PITCH + (uint32_t)cq * 16;
            cpasync16(stb + A_OFF + so, Ah + (size_t)(m0 + row) * HH + k0 + cq * 8);
        }
#pragma unroll
        for (int it = 0; it < 4; ++it) {           // B chunks: ids 0..511
            int id  = tid + it * GT;
            int row = id >> 3;
            int cq  = id & 7;
            uint32_t so = (uint32_t)row * PITCH + (uint32_t)cq * 16;
            cpasync16(stb + BH_OFF + so, Bh + (size_t)(n0 + row) * HH + k0 + cq * 8);
        }
    };

    load_stage(0, 0);
    cp_commit();

    const int arow_base = wm * 64 + (lane & 15);
    const int a_half    = (lane >> 4);
    const int brow_base = wn * 32 + ((lane >> 4) & 1) * 8 + (lane & 7);
    const int bksel     = (lane >> 3) & 1;

    for (int c = 0; c < NCHUNK; ++c) {
        if (c + 1 < NCHUNK) load_stage((c + 1) & 1, (c + 1) * KC);
        cp_commit();
        cp_wait<1>();
        __syncthreads();

        uint32_t stb = sb + (c & 1) * STAGE_BYTES;
#pragma unroll
        for (int ks = 0; ks < NKS; ++ks) {
            uint32_t acol = (ks * 2 + a_half) * 16;
            uint32_t bcol = (ks * 2 + bksel) * 16;
            uint32_t ah[4][4], bh[2][4];
#pragma unroll
            for (int mt = 0; mt < 4; ++mt)
                ldsm4(ah[mt], stb + A_OFF + (uint32_t)(arow_base + mt * 16) * PITCH + acol);
#pragma unroll
            for (int p = 0; p < 2; ++p)
                ldsm4(bh[p], stb + BH_OFF + (uint32_t)(brow_base + p * 16) * PITCH + bcol);
#pragma unroll
            for (int mt = 0; mt < 4; ++mt)
#pragma unroll
                for (int nt = 0; nt < 4; ++nt)
                    mma16816(acc[mt][nt], ah[mt], &bh[nt >> 1][(nt & 1) * 2]);
        }
        __syncthreads();
    }

    // ---- epilogue: row-wise sum(exp); policy also records CTA-local row max ----
#pragma unroll
    for (int mt = 0; mt < 4; ++mt) {
#pragma unroll
        for (int half = 0; half < 2; ++half) {
            int row = m0 + wm * 64 + mt * 16 + (lane >> 2) + half * 8;
            float s = 0.0f;
            float vmax = -3.402823466e+38f;
            unsigned am = 0;
#pragma unroll
            for (int nt = 0; nt < 4; ++nt)
#pragma unroll
                for (int j = 0; j < 2; ++j) {
                    float v = acc[mt][nt][half * 2 + j];
                    s += fexp(v);
                    unsigned col = (unsigned)(n0 + wn * 32 + nt * 8 + (lane & 3) * 2 + j);
                    if (v > vmax) { vmax = v; am = col; }
                }
#pragma unroll
            for (int m = 1; m < 4; m <<= 1) {
                s += __shfl_xor_sync(0xFFFFFFFFu, s, m);
                float ov = __shfl_xor_sync(0xFFFFFFFFu, vmax, m);
                unsigned oa = __shfl_xor_sync(0xFFFFFFFFu, am, m);
                if (ov > vmax || (ov == vmax && oa < am)) { vmax = ov; am = oa; }
            }
            if ((lane & 3) == 0) {
                atomicAdd(&sumexp[row], s);
                if (do_max) {
                    unsigned long long p = ((unsigned long long)fkey(vmax) << 32)
                                         | (unsigned long long)(0xFFFFFFFFu - am);
                    atomicMax(&cand[(size_t)row * CANDP + blockIdx.y], p);
                }
            }
        }
    }
}

// ---------------- fused: top-3 candidate scan + exact fp32 dots + pick ----------------
__global__ void gather_pick(const float* __restrict__ x, const float* __restrict__ w,
                            const float* __restrict__ rx, const float* __restrict__ rw) {
    __shared__ unsigned long long sv[256];
    __shared__ unsigned scols[3];
    __shared__ float sd[6];
    int row = blockIdx.x;
    int tid = threadIdx.x;            // 192 threads
    int wrp = tid >> 5;               // 0..5
    int lane = tid & 31;

    // ---- phase 1: top-3 over g_cand[row][0..NCTAY) ----
    const unsigned long long* cr = &g_cand[(size_t)row * CANDP];
    unsigned long long loc[3];        // this thread's strided entries (500/192 -> <=3)
    int nloc = 0;
    for (int k = tid; k < NCTAY; k += 192) loc[nloc++] = cr[k];

    unsigned long long m1, m2, m3;
    if (tid < 64) sv[192 + tid] = 0ull;
    {
        unsigned long long v = 0ull;
        for (int k = 0; k < nloc; ++k) v = (loc[k] > v) ? loc[k] : v;
        sv[tid] = v; __syncthreads();
        for (int s = 128; s > 0; s >>= 1) {
            if (tid < s) sv[tid] = (sv[tid] > sv[tid + s]) ? sv[tid] : sv[tid + s];
            __syncthreads();
        }
        m1 = sv[0]; __syncthreads();
    }
    {
        unsigned long long v = 0ull;
        for (int k = 0; k < nloc; ++k)
            if (loc[k] != m1) v = (loc[k] > v) ? loc[k] : v;
        sv[tid] = v; __syncthreads();
        for (int s = 128; s > 0; s >>= 1) {
            if (tid < s) sv[tid] = (sv[tid] > sv[tid + s]) ? sv[tid] : sv[tid + s];
            __syncthreads();
        }
        m2 = sv[0]; __syncthreads();
    }
    {
        unsigned long long v = 0ull;
        for (int k = 0; k < nloc; ++k)
            if (loc[k] != m1 && loc[k] != m2) v = (loc[k] > v) ? loc[k] : v;
        sv[tid] = v; __syncthreads();
        for (int s = 128; s > 0; s >>= 1) {
            if (tid < s) sv[tid] = (sv[tid] > sv[tid + s]) ? sv[tid] : sv[tid + s];
            __syncthreads();
        }
        m3 = sv[0];
    }
    if (tid == 0) {
        unsigned c1 = 0xFFFFFFFFu - (unsigned)(m1 & 0xFFFFFFFFull);
        unsigned c2 = (m2 != 0ull) ? (0xFFFFFFFFu - (unsigned)(m2 & 0xFFFFFFFFull)) : c1;
        unsigned c3 = (m3 != 0ull) ? (0xFFFFFFFFu - (unsigned)(m3 & 0xFFFFFFFFull)) : c1;
        scols[0] = c1; scols[1] = c2; scols[2] = c3;
    }
    __syncthreads();

    // ---- phase 2: exact fp32 dots for (model, cand) = (wrp/3, wrp%3) ----
    unsigned col = scols[wrp % 3];
    const float* a = (wrp < 3) ? (x + (size_t)row * HH) : (rx + (size_t)row * HH);
    const float* b = (wrp < 3) ? (w + (size_t)col * HH) : (rw + (size_t)col * HH);
    float s = 0.0f;
    for (int h = lane; h < HH; h += 32) s = fmaf(a[h], b[h], s);
#pragma unroll
    for (int m = 16; m >= 1; m >>= 1) s += __shfl_xor_sync(0xFFFFFFFFu, s, m);
    if (lane == 0) sd[wrp] = s;
    __syncthreads();
    if (tid == 0) {
        int best = 0;
        for (int k = 1; k < 3; ++k) {
            if (sd[k] > sd[best] || (sd[k] == sd[best] && scols[k] < scols[best])) best = k;
        }
        g_pdot[row] = sd[best];
        g_rdot[row] = sd[3 + best];
    }
}

// ---------------- final scalar loss ----------------
__global__ void loss_kernel(const float* __restrict__ adv,
                            const float* __restrict__ oldlp,
                            const int*   __restrict__ mask,
                            float* __restrict__ out) {
    __shared__ float sl[256], sm[256];
    int tid = threadIdx.x;
    float accl = 0.0f, accm = 0.0f;
    for (int r = tid; r < BT; r += 256) {
        int b = r / TT;
        float lse_p = logf(g_sum_pol[r]);
        float lse_r = logf(g_sum_ref[r]);
        float chosen_lp = g_pdot[r] - lse_p;
        float ref_lp    = g_rdot[r] - lse_r;

        float c1 = expf(chosen_lp - oldlp[r]);
        float c2 = fminf(fmaxf(c1, 1.0f - EPS_LO_C), 1.0f + EPS_HI_C);
        float a  = adv[b];
        float ptl = -fminf(c1 * a, c2 * a);

        float delta = ref_lp - chosen_lp;
        float kl = expf(delta) - delta - 1.0f;
        ptl += BETA_C * kl;

        float m = (float)mask[r];
        accl += ptl * m;
        accm += m;
    }
    sl[tid] = accl; sm[tid] = accm;
    __syncthreads();
    for (int s = 128; s > 0; s >>= 1) {
        if (tid < s) { sl[tid] += sl[tid + s]; sm[tid] += sm[tid + s]; }
        __syncthreads();
    }
    if (tid == 0) out[0] = sl[0] / fmaxf(sm[0], 1.0f);
}

// ---------------- launch ----------------
extern "C" void kernel_launch(void* const* d_in, const int* in_sizes, int n_in,
                              void* d_out, int out_size) {
    const float* x    = (const float*)d_in[0];
    const float* w    = (const float*)d_in[1];
    const float* rx   = (const float*)d_in[2];
    const float* rw   = (const float*)d_in[3];
    const float* adv  = (const float*)d_in[4];
    const float* oldl = (const float*)d_in[5];
    const int*   msk  = (const int*)d_in[6];
    float* out = (float*)d_out;

    float *sum_pol, *sum_ref;
    unsigned long long* cand;
    __half *xh, *wh, *rxh, *rwh;
    cudaGetSymbolAddress((void**)&sum_pol, g_sum_pol);
    cudaGetSymbolAddress((void**)&sum_ref, g_sum_ref);
    cudaGetSymbolAddress((void**)&cand,    g_cand);
    cudaGetSymbolAddress((void**)&xh,  g_xh);
    cudaGetSymbolAddress((void**)&wh,  g_wh);
    cudaGetSymbolAddress((void**)&rxh, g_rxh);
    cudaGetSymbolAddress((void**)&rwh, g_rwh);

    cudaFuncSetAttribute(gemm_mma, cudaFuncAttributeMaxDynamicSharedMemorySize, SMEM_DYN);

    init_kernel<<<(BT * CANDP + 255) / 256, 256>>>();

    convert_all<<<(NTOT + 255) / 256, 256>>>(x, rx, w, rw, xh, rxh, wh, rwh);

    dim3 grid(BT / BM, VV / BN);   // (16, 500)
    gemm_mma<<<grid, GT, SMEM_DYN>>>(xh,  wh,  sum_pol, cand, 1);
    gemm_mma<<<grid, GT, SMEM_DYN>>>(rxh, rwh, sum_ref, cand, 0);

    gather_pick<<<BT, 192>>>(x, w, rx, rw);
    loss_kernel<<<1, 256>>>(adv, oldl, msk, out);
}

// round 16
// speedup vs baseline: 1.0451x; 1.0121x over previous
#include <cuda_runtime.h>
#include <cuda_bf16.h>
#include <cuda_fp16.h>
#include <math.h>
#include <stdint.h>

// Problem constants
#define BB   4
#define TT   512
#define HH   2048
#define VV   32000
#define BT   (BB*TT)          // 2048 rows
#define NCTAY 500
#define CANDP 512             // padded stride for candidate table
#define BETA_C   0.1f
#define EPS_LO_C 0.2f
#define EPS_HI_C 0.2f

// GEMM tiling (legacy mma.sync path; tcgen05 not available on this target)
#define BM 128
#define BN 64                  // narrow CTA -> 4 CTAs/SM, 4 barrier domains
#define KC 64                  // K chunk in fp16 elems
#define NKS (KC/16)            // 4 ks-steps per chunk
#define NCHUNK (HH/KC)         // 32
#define NST 2                  // 2-stage: empirical optimum
#define PITCH 144              // 128B data + 16B pad; conflict-free for LDSM
#define A_OFF  0
#define BH_OFF 18432           // 128 rows * 144
#define STAGE_BYTES 27648      // + 64 rows * 144
#define SMEM_DYN (NST*STAGE_BYTES)   // 55296 -> 4 CTAs/SM
#define GT 128                 // threads per CTA

// ---------------- scratch (static device globals; no allocations) ----------------
__device__ float              g_sum_pol[BT];
__device__ float              g_sum_ref[BT];
__device__ unsigned long long g_cand[BT*CANDP];   // per (row, ctaY) noisy max
__device__ float              g_pdot[BT];
__device__ float              g_rdot[BT];
__device__ __align__(1024) __half g_xh [BT*HH];
__device__ __align__(1024) __half g_wh [(size_t)VV*HH];
__device__ __align__(1024) __half g_rxh[BT*HH];
__device__ __align__(1024) __half g_rwh[(size_t)VV*HH];

// ---------------- PTX helpers ----------------
__device__ __forceinline__ uint32_t s2u(const void* p) {
    uint32_t a;
    asm("{ .reg .u64 t; cvta.to.shared.u64 t, %1; cvt.u32.u64 %0, t; }" : "=r"(a) : "l"(p));
    return a;
}
__device__ __forceinline__ void cpasync16(uint32_t s, const void* g) {
    asm volatile("cp.async.cg.shared.global [%0], [%1], 16;" :: "r"(s), "l"(g) : "memory");
}
__device__ __forceinline__ void cp_commit() {
    asm volatile("cp.async.commit_group;" ::: "memory");
}
template <int N>
__device__ __forceinline__ void cp_wait() {
    asm volatile("cp.async.wait_group %0;" :: "n"(N) : "memory");
}
__device__ __forceinline__ void ldsm4(uint32_t* r, uint32_t a) {
    asm volatile("ldmatrix.sync.aligned.m8n8.x4.shared.b16 {%0,%1,%2,%3}, [%4];"
                 : "=r"(r[0]), "=r"(r[1]), "=r"(r[2]), "=r"(r[3]) : "r"(a));
}
__device__ __forceinline__ void mma16816(float* d, const uint32_t* a, const uint32_t* b) {
    asm volatile(
        "mma.sync.aligned.m16n8k16.row.col.f32.f16.f16.f32 "
        "{%0,%1,%2,%3}, {%4,%5,%6,%7}, {%8,%9}, {%0,%1,%2,%3};"
        : "+f"(d[0]), "+f"(d[1]), "+f"(d[2]), "+f"(d[3])
        : "r"(a[0]), "r"(a[1]), "r"(a[2]), "r"(a[3]), "r"(b[0]), "r"(b[1]));
}
__device__ __forceinline__ unsigned fkey(float f) {
    unsigned u = __float_as_uint(f);
    return (u & 0x80000000u) ? ~u : (u | 0x80000000u);
}
// FMA-only exp
__device__ __forceinline__ float fexp(float x) {
    float t = x * 1.4426950408889634f;
    float r = rintf(t);
    float u = (t - r) * 0.6931471805599453f;
    float p = 8.3333333e-3f;
    p = fmaf(p, u, 4.1666667e-2f);
    p = fmaf(p, u, 1.6666667e-1f);
    p = fmaf(p, u, 0.5f);
    p = fmaf(p, u, 1.0f);
    p = fmaf(p, u, 1.0f);
    int e = (int)r;
    return p * __int_as_float((e + 127) << 23);
}

// ---------------- convert one (activation, weight) pair; optional scratch init ----------------
#define NXI (BT*HH/8)                       // 524288 items per activation tensor
#define NWI ((int)((size_t)VV*HH/8))        // 8192000 items per weight tensor
#define NPAIR (NXI + NWI)                   // 8716288

__global__ void convert_pair(const float* __restrict__ act, const float* __restrict__ wt,
                             __half* __restrict__ acth, __half* __restrict__ wth,
                             int do_init) {
    int i = blockIdx.x * blockDim.x + threadIdx.x;
    if (do_init) {
        if (i < BT) { g_sum_pol[i] = 0.0f; g_sum_ref[i] = 0.0f; }
        if (i < BT * CANDP) g_cand[i] = 0ull;
    }
    if (i >= NPAIR) return;
    const float* src;
    __half* dst;
    int j;
    if (i < NXI) { src = act; dst = acth; j = i; }
    else         { src = wt;  dst = wth;  j = i - NXI; }

    float4 v0 = ((const float4*)src)[2*(size_t)j];
    float4 v1 = ((const float4*)src)[2*(size_t)j+1];
    __half2 h[4];
    h[0] = __floats2half2_rn(v0.x, v0.y);
    h[1] = __floats2half2_rn(v0.z, v0.w);
    h[2] = __floats2half2_rn(v1.x, v1.y);
    h[3] = __floats2half2_rn(v1.z, v1.w);
    ((uint4*)dst)[(size_t)j] = *(uint4*)h;
}

// ---------------- single-fp16 tensor-core GEMM + fused softmax-stats ----------------
__global__ void __launch_bounds__(GT, 4)
gemm_mma(const __half* __restrict__ Ah, const __half* __restrict__ Bh,
         float* __restrict__ sumexp, unsigned long long* __restrict__ cand,
         int do_max) {
    extern __shared__ char smem[];
    const uint32_t sb = s2u(smem);
    const int tid  = threadIdx.x;
    const int lane = tid & 31;
    const int wid  = tid >> 5;         // 0..3
    const int wm   = wid >> 1;          // 0..1 (64-row slab)
    const int wn   = wid & 1;           // 0..1 (32-col slab)
    const int m0 = blockIdx.x * BM;
    const int n0 = blockIdx.y * BN;

    float acc[4][4][4];
#pragma unroll
    for (int mt = 0; mt < 4; ++mt)
#pragma unroll
        for (int nt = 0; nt < 4; ++nt)
#pragma unroll
            for (int j = 0; j < 4; ++j) acc[mt][nt][j] = 0.0f;

    // cp.async per stage: A 128 rows x 8 chunks = 1024, B 64 x 8 = 512 -> 12/thread
    auto load_stage = [&](int st, int k0) {
        uint32_t stb = sb + st * STAGE_BYTES;
#pragma unroll
        for (int it = 0; it < 8; ++it) {           // A chunks: ids 0..1023
            int id  = tid + it * GT;
            int row = id >> 3;
            int cq  = id & 7;
            uint32_t so = (uint32_t)row * PITCH + (uint32_t)cq * 16;
            cpasync16(stb + A_OFF + so, Ah + (size_t)(m0 + row) * HH + k0 + cq * 8);
        }
#pragma unroll
        for (int it = 0; it < 4; ++it) {           // B chunks: ids 0..511
            int id  = tid + it * GT;
            int row = id >> 3;
            int cq  = id & 7;
            uint32_t so = (uint32_t)row * PITCH + (uint32_t)cq * 16;
            cpasync16(stb + BH_OFF + so, Bh + (size_t)(n0 + row) * HH + k0 + cq * 8);
        }
    };

    load_stage(0, 0);
    cp_commit();

    const int arow_base = wm * 64 + (lane & 15);
    const int a_half    = (lane >> 4);
    const int brow_base = wn * 32 + ((lane >> 4) & 1) * 8 + (lane & 7);
    const int bksel     = (lane >> 3) & 1;

    for (int c = 0; c < NCHUNK; ++c) {
        if (c + 1 < NCHUNK) load_stage((c + 1) & 1, (c + 1) * KC);
        cp_commit();
        cp_wait<1>();
        __syncthreads();

        uint32_t stb = sb + (c & 1) * STAGE_BYTES;
#pragma unroll
        for (int ks = 0; ks < NKS; ++ks) {
            uint32_t acol = (ks * 2 + a_half) * 16;
            uint32_t bcol = (ks * 2 + bksel) * 16;
            uint32_t ah[4][4], bh[2][4];
#pragma unroll
            for (int mt = 0; mt < 4; ++mt)
                ldsm4(ah[mt], stb + A_OFF + (uint32_t)(arow_base + mt * 16) * PITCH + acol);
#pragma unroll
            for (int p = 0; p < 2; ++p)
                ldsm4(bh[p], stb + BH_OFF + (uint32_t)(brow_base + p * 16) * PITCH + bcol);
#pragma unroll
            for (int mt = 0; mt < 4; ++mt)
#pragma unroll
                for (int nt = 0; nt < 4; ++nt)
                    mma16816(acc[mt][nt], ah[mt], &bh[nt >> 1][(nt & 1) * 2]);
        }
        __syncthreads();
    }

    // ---- epilogue: row-wise sum(exp); policy also records CTA-local row max ----
#pragma unroll
    for (int mt = 0; mt < 4; ++mt) {
#pragma unroll
        for (int half = 0; half < 2; ++half) {
            int row = m0 + wm * 64 + mt * 16 + (lane >> 2) + half * 8;
            float s = 0.0f;
            float vmax = -3.402823466e+38f;
            unsigned am = 0;
#pragma unroll
            for (int nt = 0; nt < 4; ++nt)
#pragma unroll
                for (int j = 0; j < 2; ++j) {
                    float v = acc[mt][nt][half * 2 + j];
                    s += fexp(v);
                    unsigned col = (unsigned)(n0 + wn * 32 + nt * 8 + (lane & 3) * 2 + j);
                    if (v > vmax) { vmax = v; am = col; }
                }
#pragma unroll
            for (int m = 1; m < 4; m <<= 1) {
                s += __shfl_xor_sync(0xFFFFFFFFu, s, m);
                float ov = __shfl_xor_sync(0xFFFFFFFFu, vmax, m);
                unsigned oa = __shfl_xor_sync(0xFFFFFFFFu, am, m);
                if (ov > vmax || (ov == vmax && oa < am)) { vmax = ov; am = oa; }
            }
            if ((lane & 3) == 0) {
                atomicAdd(&sumexp[row], s);
                if (do_max) {
                    unsigned long long p = ((unsigned long long)fkey(vmax) << 32)
                                         | (unsigned long long)(0xFFFFFFFFu - am);
                    atomicMax(&cand[(size_t)row * CANDP + blockIdx.y], p);
                }
            }
        }
    }
}

// ---------------- fused: top-3 candidate scan + exact fp32 dots + pick ----------------
__global__ void gather_pick(const float* __restrict__ x, const float* __restrict__ w,
                            const float* __restrict__ rx, const float* __restrict__ rw) {
    __shared__ unsigned long long sv[256];
    __shared__ unsigned scols[3];
    __shared__ float sd[6];
    int row = blockIdx.x;
    int tid = threadIdx.x;            // 192 threads
    int wrp = tid >> 5;               // 0..5
    int lane = tid & 31;

    // ---- phase 1: top-3 over g_cand[row][0..NCTAY) ----
    const unsigned long long* cr = &g_cand[(size_t)row * CANDP];
    unsigned long long loc[3];        // this thread's strided entries (500/192 -> <=3)
    int nloc = 0;
    for (int k = tid; k < NCTAY; k += 192) loc[nloc++] = cr[k];

    unsigned long long m1, m2, m3;
    if (tid < 64) sv[192 + tid] = 0ull;
    {
        unsigned long long v = 0ull;
        for (int k = 0; k < nloc; ++k) v = (loc[k] > v) ? loc[k] : v;
        sv[tid] = v; __syncthreads();
        for (int s = 128; s > 0; s >>= 1) {
            if (tid < s) sv[tid] = (sv[tid] > sv[tid + s]) ? sv[tid] : sv[tid + s];
            __syncthreads();
        }
        m1 = sv[0]; __syncthreads();
    }
    {
        unsigned long long v = 0ull;
        for (int k = 0; k < nloc; ++k)
            if (loc[k] != m1) v = (loc[k] > v) ? loc[k] : v;
        sv[tid] = v; __syncthreads();
        for (int s = 128; s > 0; s >>= 1) {
            if (tid < s) sv[tid] = (sv[tid] > sv[tid + s]) ? sv[tid] : sv[tid + s];
            __syncthreads();
        }
        m2 = sv[0]; __syncthreads();
    }
    {
        unsigned long long v = 0ull;
        for (int k = 0; k < nloc; ++k)
            if (loc[k] != m1 && loc[k] != m2) v = (loc[k] > v) ? loc[k] : v;
        sv[tid] = v; __syncthreads();
        for (int s = 128; s > 0; s >>= 1) {
            if (tid < s) sv[tid] = (sv[tid] > sv[tid + s]) ? sv[tid] : sv[tid + s];
            __syncthreads();
        }
        m3 = sv[0];
    }
    if (tid == 0) {
        unsigned c1 = 0xFFFFFFFFu - (unsigned)(m1 & 0xFFFFFFFFull);
        unsigned c2 = (m2 != 0ull) ? (0xFFFFFFFFu - (unsigned)(m2 & 0xFFFFFFFFull)) : c1;
        unsigned c3 = (m3 != 0ull) ? (0xFFFFFFFFu - (unsigned)(m3 & 0xFFFFFFFFull)) : c1;
        scols[0] = c1; scols[1] = c2; scols[2] = c3;
    }
    __syncthreads();

    // ---- phase 2: exact fp32 dots for (model, cand) = (wrp/3, wrp%3) ----
    unsigned col = scols[wrp % 3];
    const float* a = (wrp < 3) ? (x + (size_t)row * HH) : (rx + (size_t)row * HH);
    const float* b = (wrp < 3) ? (w + (size_t)col * HH) : (rw + (size_t)col * HH);
    float s = 0.0f;
    for (int h = lane; h < HH; h += 32) s = fmaf(a[h], b[h], s);
#pragma unroll
    for (int m = 16; m >= 1; m >>= 1) s += __shfl_xor_sync(0xFFFFFFFFu, s, m);
    if (lane == 0) sd[wrp] = s;
    __syncthreads();
    if (tid == 0) {
        int best = 0;
        for (int k = 1; k < 3; ++k) {
            if (sd[k] > sd[best] || (sd[k] == sd[best] && scols[k] < scols[best])) best = k;
        }
        g_pdot[row] = sd[best];
        g_rdot[row] = sd[3 + best];
    }
}

// ---------------- final scalar loss ----------------
__global__ void loss_kernel(const float* __restrict__ adv,
                            const float* __restrict__ oldlp,
                            const int*   __restrict__ mask,
                            float* __restrict__ out) {
    __shared__ float sl[256], sm[256];
    int tid = threadIdx.x;
    float accl = 0.0f, accm = 0.0f;
    for (int r = tid; r < BT; r += 256) {
        int b = r / TT;
        float lse_p = logf(g_sum_pol[r]);
        float lse_r = logf(g_sum_ref[r]);
        float chosen_lp = g_pdot[r] - lse_p;
        float ref_lp    = g_rdot[r] - lse_r;

        float c1 = expf(chosen_lp - oldlp[r]);
        float c2 = fminf(fmaxf(c1, 1.0f - EPS_LO_C), 1.0f + EPS_HI_C);
        float a  = adv[b];
        float ptl = -fminf(c1 * a, c2 * a);

        float delta = ref_lp - chosen_lp;
        float kl = expf(delta) - delta - 1.0f;
        ptl += BETA_C * kl;

        float m = (float)mask[r];
        accl += ptl * m;
        accm += m;
    }
    sl[tid] = accl; sm[tid] = accm;
    __syncthreads();
    for (int s = 128; s > 0; s >>= 1) {
        if (tid < s) { sl[tid] += sl[tid + s]; sm[tid] += sm[tid + s]; }
        __syncthreads();
    }
    if (tid == 0) out[0] = sl[0] / fmaxf(sm[0], 1.0f);
}

// ---------------- launch (fork-join graph: converts/gather overlap GEMMs) ----------------
extern "C" void kernel_launch(void* const* d_in, const int* in_sizes, int n_in,
                              void* d_out, int out_size) {
    const float* x    = (const float*)d_in[0];
    const float* w    = (const float*)d_in[1];
    const float* rx   = (const float*)d_in[2];
    const float* rw   = (const float*)d_in[3];
    const float* adv  = (const float*)d_in[4];
    const float* oldl = (const float*)d_in[5];
    const int*   msk  = (const int*)d_in[6];
    float* out = (float*)d_out;

    float *sum_pol, *sum_ref;
    unsigned long long* cand;
    __half *xh, *wh, *rxh, *rwh;
    cudaGetSymbolAddress((void**)&sum_pol, g_sum_pol);
    cudaGetSymbolAddress((void**)&sum_ref, g_sum_ref);
    cudaGetSymbolAddress((void**)&cand,    g_cand);
    cudaGetSymbolAddress((void**)&xh,  g_xh);
    cudaGetSymbolAddress((void**)&wh,  g_wh);
    cudaGetSymbolAddress((void**)&rxh, g_rxh);
    cudaGetSymbolAddress((void**)&rwh, g_rwh);

    cudaFuncSetAttribute(gemm_mma, cudaFuncAttributeMaxDynamicSharedMemorySize, SMEM_DYN);

    // side stream + events (host-side objects only; created fresh per call —
    // kernel_launch is invoked only for correctness + capture, replays are graph-only)
    cudaStream_t s2;
    cudaStreamCreateWithFlags(&s2, cudaStreamNonBlocking);
    cudaEvent_t eFork, eRefCvt, ePolDone, eGather;
    cudaEventCreateWithFlags(&eFork,    cudaEventDisableTiming);
    cudaEventCreateWithFlags(&eRefCvt,  cudaEventDisableTiming);
    cudaEventCreateWithFlags(&ePolDone, cudaEventDisableTiming);
    cudaEventCreateWithFlags(&eGather,  cudaEventDisableTiming);

    const int ncb = (NPAIR + 255) / 256;
    dim3 grid(BT / BM, VV / BN);   // (16, 500)

    // fork s2 off the main (capture) stream
    cudaEventRecord(eFork, 0);
    cudaStreamWaitEvent(s2, eFork, 0);

    // main: policy convert (+ scratch init) -> policy GEMM
    convert_pair<<<ncb, 256>>>(x, w, xh, wh, 1);
    gemm_mma<<<grid, GT, SMEM_DYN>>>(xh, wh, sum_pol, cand, 1);
    cudaEventRecord(ePolDone, 0);

    // s2: ref convert overlaps policy GEMM
    convert_pair<<<ncb, 256, 0, s2>>>(rx, rw, rxh, rwh, 0);
    cudaEventRecord(eRefCvt, s2);

    // s2: gather_pick needs policy candidates only -> overlaps ref GEMM
    cudaStreamWaitEvent(s2, ePolDone, 0);
    gather_pick<<<BT, 192, 0, s2>>>(x, w, rx, rw);
    cudaEventRecord(eGather, s2);

    // main: ref GEMM (after ref convert), then loss (after gather too)
    cudaStreamWaitEvent(0, eRefCvt, 0);
    gemm_mma<<<grid, GT, SMEM_DYN>>>(rxh, rwh, sum_ref, cand, 0);
    cudaStreamWaitEvent(0, eGather, 0);
    loss_kernel<<<1, 256>>>(adv, oldl, msk, out);

    cudaEventDestroy(eFork);
    cudaEventDestroy(eRefCvt);
    cudaEventDestroy(ePolDone);
    cudaEventDestroy(eGather);
    cudaStreamDestroy(s2);
}

// round 17
// speedup vs baseline: 1.0467x; 1.0015x over previous
#include <cuda_runtime.h>
#include <cuda_bf16.h>
#include <cuda_fp16.h>
#include <math.h>
#include <stdint.h>

// Problem constants
#define BB   4
#define TT   512
#define HH   2048
#define VV   32000
#define BT   (BB*TT)          // 2048 rows
#define NCTAY 500
#define CANDP 512             // padded stride for candidate table
#define BETA_C   0.1f
#define EPS_LO_C 0.2f
#define EPS_HI_C 0.2f

// GEMM tiling (legacy mma.sync path; tcgen05 not available on this target)
#define BM 128
#define BN 64                  // narrow CTA -> 4 CTAs/SM, 4 barrier domains
#define KC 64                  // K chunk in fp16 elems
#define NKS (KC/16)            // 4 ks-steps per chunk
#define NCHUNK (HH/KC)         // 32
#define NST 2                  // 2-stage: empirical optimum
#define PITCH 144              // 128B data + 16B pad; conflict-free for LDSM
#define A_OFF  0
#define BH_OFF 18432           // 128 rows * 144
#define STAGE_BYTES 27648      // + 64 rows * 144
#define SMEM_DYN (NST*STAGE_BYTES)   // 55296 -> 4 CTAs/SM
#define GT 128                 // threads per CTA

// ---------------- scratch (static device globals; no allocations) ----------------
__device__ float              g_sum_pol[BT];
__device__ float              g_sum_ref[BT];
__device__ unsigned long long g_cand[BT*CANDP];   // per (row, ctaY) noisy max
__device__ float              g_pdot[BT];
__device__ float              g_rdot[BT];
__device__ __align__(1024) __half g_xh [BT*HH];
__device__ __align__(1024) __half g_wh [(size_t)VV*HH];
__device__ __align__(1024) __half g_rxh[BT*HH];
__device__ __align__(1024) __half g_rwh[(size_t)VV*HH];

// ---------------- PTX helpers ----------------
__device__ __forceinline__ uint32_t s2u(const void* p) {
    uint32_t a;
    asm("{ .reg .u64 t; cvta.to.shared.u64 t, %1; cvt.u32.u64 %0, t; }" : "=r"(a) : "l"(p));
    return a;
}
__device__ __forceinline__ void cpasync16(uint32_t s, const void* g) {
    asm volatile("cp.async.cg.shared.global [%0], [%1], 16;" :: "r"(s), "l"(g) : "memory");
}
__device__ __forceinline__ void cp_commit() {
    asm volatile("cp.async.commit_group;" ::: "memory");
}
template <int N>
__device__ __forceinline__ void cp_wait() {
    asm volatile("cp.async.wait_group %0;" :: "n"(N) : "memory");
}
__device__ __forceinline__ void ldsm4(uint32_t* r, uint32_t a) {
    asm volatile("ldmatrix.sync.aligned.m8n8.x4.shared.b16 {%0,%1,%2,%3}, [%4];"
                 : "=r"(r[0]), "=r"(r[1]), "=r"(r[2]), "=r"(r[3]) : "r"(a));
}
__device__ __forceinline__ void mma16816(float* d, const uint32_t* a, const uint32_t* b) {
    asm volatile(
        "mma.sync.aligned.m16n8k16.row.col.f32.f16.f16.f32 "
        "{%0,%1,%2,%3}, {%4,%5,%6,%7}, {%8,%9}, {%0,%1,%2,%3};"
        : "+f"(d[0]), "+f"(d[1]), "+f"(d[2]), "+f"(d[3])
        : "r"(a[0]), "r"(a[1]), "r"(a[2]), "r"(a[3]), "r"(b[0]), "r"(b[1]));
}
__device__ __forceinline__ unsigned fkey(float f) {
    unsigned u = __float_as_uint(f);
    return (u & 0x80000000u) ? ~u : (u | 0x80000000u);
}
// FMA-only exp
__device__ __forceinline__ float fexp(float x) {
    float t = x * 1.4426950408889634f;
    float r = rintf(t);
    float u = (t - r) * 0.6931471805599453f;
    float p = 8.3333333e-3f;
    p = fmaf(p, u, 4.1666667e-2f);
    p = fmaf(p, u, 1.6666667e-1f);
    p = fmaf(p, u, 0.5f);
    p = fmaf(p, u, 1.0f);
    p = fmaf(p, u, 1.0f);
    int e = (int)r;
    return p * __int_as_float((e + 127) << 23);
}

// ---------------- convert one (activation, weight) pair; optional scratch init ----------------
#define NXI (BT*HH/8)                       // 524288 items per activation tensor
#define NWI ((int)((size_t)VV*HH/8))        // 8192000 items per weight tensor
#define NPAIR (NXI + NWI)                   // 8716288

__global__ void convert_pair(const float* __restrict__ act, const float* __restrict__ wt,
                             __half* __restrict__ acth, __half* __restrict__ wth,
                             int do_init) {
    int i = blockIdx.x * blockDim.x + threadIdx.x;
    if (do_init) {
        if (i < BT) { g_sum_pol[i] = 0.0f; g_sum_ref[i] = 0.0f; }
        if (i < BT * CANDP) g_cand[i] = 0ull;
    }
    if (i >= NPAIR) return;
    const float* src;
    __half* dst;
    int j;
    if (i < NXI) { src = act; dst = acth; j = i; }
    else         { src = wt;  dst = wth;  j = i - NXI; }

    float4 v0 = ((const float4*)src)[2*(size_t)j];
    float4 v1 = ((const float4*)src)[2*(size_t)j+1];
    __half2 h[4];
    h[0] = __floats2half2_rn(v0.x, v0.y);
    h[1] = __floats2half2_rn(v0.z, v0.w);
    h[2] = __floats2half2_rn(v1.x, v1.y);
    h[3] = __floats2half2_rn(v1.z, v1.w);
    ((uint4*)dst)[(size_t)j] = *(uint4*)h;
}

// ---------------- single-fp16 tensor-core GEMM + fused softmax-stats ----------------
__global__ void __launch_bounds__(GT, 4)
gemm_mma(const __half* __restrict__ Ah, const __half* __restrict__ Bh,
         float* __restrict__ sumexp, unsigned long long* __restrict__ cand,
         int do_max) {
    extern __shared__ char smem[];
    const uint32_t sb = s2u(smem);
    const int tid  = threadIdx.x;
    const int lane = tid & 31;
    const int wid  = tid >> 5;         // 0..3
    const int wm   = wid >> 1;          // 0..1 (64-row slab)
    const int wn   = wid & 1;           // 0..1 (32-col slab)
    const int m0 = blockIdx.x * BM;
    const int n0 = blockIdx.y * BN;

    float acc[4][4][4];
#pragma unroll
    for (int mt = 0; mt < 4; ++mt)
#pragma unroll
        for (int nt = 0; nt < 4; ++nt)
#pragma unroll
            for (int j = 0; j < 4; ++j) acc[mt][nt][j] = 0.0f;

    // cp.async per stage: A 128 rows x 8 chunks = 1024, B 64 x 8 = 512 -> 12/thread
    auto load_stage = [&](int st, int k0) {
        uint32_t stb = sb + st * STAGE_BYTES;
#pragma unroll
        for (int it = 0; it < 8; ++it) {           // A chunks: ids 0..1023
            int id  = tid + it * GT;
            int row = id >> 3;
            int cq  = id & 7;
            uint32_t so = (uint32_t)row * PITCH + (uint32_t)cq * 16;
            cpasync16(stb + A_OFF + so, Ah + (size_t)(m0 + row) * HH + k0 + cq * 8);
        }
#pragma unroll
        for (int it = 0; it < 4; ++it) {           // B chunks: ids 0..511
            int id  = tid + it * GT;
            int row = id >> 3;
            int cq  = id & 7;
            uint32_t so = (uint32_t)row * PITCH + (uint32_t)cq * 16;
            cpasync16(stb + BH_OFF + so, Bh + (size_t)(n0 + row) * HH + k0 + cq * 8);
        }
    };

    load_stage(0, 0);
    cp_commit();

    const int arow_base = wm * 64 + (lane & 15);
    const int a_half    = (lane >> 4);
    const int brow_base = wn * 32 + ((lane >> 4) & 1) * 8 + (lane & 7);
    const int bksel     = (lane >> 3) & 1;

    for (int c = 0; c < NCHUNK; ++c) {
        if (c + 1 < NCHUNK) load_stage((c + 1) & 1, (c + 1) * KC);
        cp_commit();
        cp_wait<1>();
        __syncthreads();

        uint32_t stb = sb + (c & 1) * STAGE_BYTES;
#pragma unroll
        for (int ks = 0; ks < NKS; ++ks) {
            uint32_t acol = (ks * 2 + a_half) * 16;
            uint32_t bcol = (ks * 2 + bksel) * 16;
            uint32_t ah[4][4], bh[2][4];
#pragma unroll
            for (int mt = 0; mt < 4; ++mt)
                ldsm4(ah[mt], stb + A_OFF + (uint32_t)(arow_base + mt * 16) * PITCH + acol);
#pragma unroll
            for (int p = 0; p < 2; ++p)
                ldsm4(bh[p], stb + BH_OFF + (uint32_t)(brow_base + p * 16) * PITCH + bcol);
#pragma unroll
            for (int mt = 0; mt < 4; ++mt)
#pragma unroll
                for (int nt = 0; nt < 4; ++nt)
                    mma16816(acc[mt][nt], ah[mt], &bh[nt >> 1][(nt & 1) * 2]);
        }
        __syncthreads();
    }

    // ---- epilogue: row-wise sum(exp); policy also records CTA-local row max ----
#pragma unroll
    for (int mt = 0; mt < 4; ++mt) {
#pragma unroll
        for (int half = 0; half < 2; ++half) {
            int row = m0 + wm * 64 + mt * 16 + (lane >> 2) + half * 8;
            float s = 0.0f;
            float vmax = -3.402823466e+38f;
            unsigned am = 0;
#pragma unroll
            for (int nt = 0; nt < 4; ++nt)
#pragma unroll
                for (int j = 0; j < 2; ++j) {
                    float v = acc[mt][nt][half * 2 + j];
                    s += fexp(v);
                    unsigned col = (unsigned)(n0 + wn * 32 + nt * 8 + (lane & 3) * 2 + j);
                    if (v > vmax) { vmax = v; am = col; }
                }
#pragma unroll
            for (int m = 1; m < 4; m <<= 1) {
                s += __shfl_xor_sync(0xFFFFFFFFu, s, m);
                float ov = __shfl_xor_sync(0xFFFFFFFFu, vmax, m);
                unsigned oa = __shfl_xor_sync(0xFFFFFFFFu, am, m);
                if (ov > vmax || (ov == vmax && oa < am)) { vmax = ov; am = oa; }
            }
            if ((lane & 3) == 0) {
                atomicAdd(&sumexp[row], s);
                if (do_max) {
                    unsigned long long p = ((unsigned long long)fkey(vmax) << 32)
                                         | (unsigned long long)(0xFFFFFFFFu - am);
                    atomicMax(&cand[(size_t)row * CANDP + blockIdx.y], p);
                }
            }
        }
    }
}

// ---------------- fused: top-3 candidate scan + exact fp32 dots + pick ----------------
__global__ void gather_pick(const float* __restrict__ x, const float* __restrict__ w,
                            const float* __restrict__ rx, const float* __restrict__ rw) {
    __shared__ unsigned long long sv[256];
    __shared__ unsigned scols[3];
    __shared__ float sd[6];
    int row = blockIdx.x;
    int tid = threadIdx.x;            // 192 threads
    int wrp = tid >> 5;               // 0..5
    int lane = tid & 31;

    // ---- phase 1: top-3 over g_cand[row][0..NCTAY) ----
    const unsigned long long* cr = &g_cand[(size_t)row * CANDP];
    unsigned long long loc[3];        // this thread's strided entries (500/192 -> <=3)
    int nloc = 0;
    for (int k = tid; k < NCTAY; k += 192) loc[nloc++] = cr[k];

    unsigned long long m1, m2, m3;
    if (tid < 64) sv[192 + tid] = 0ull;
    {
        unsigned long long v = 0ull;
        for (int k = 0; k < nloc; ++k) v = (loc[k] > v) ? loc[k] : v;
        sv[tid] = v; __syncthreads();
        for (int s = 128; s > 0; s >>= 1) {
            if (tid < s) sv[tid] = (sv[tid] > sv[tid + s]) ? sv[tid] : sv[tid + s];
            __syncthreads();
        }
        m1 = sv[0]; __syncthreads();
    }
    {
        unsigned long long v = 0ull;
        for (int k = 0; k < nloc; ++k)
            if (loc[k] != m1) v = (loc[k] > v) ? loc[k] : v;
        sv[tid] = v; __syncthreads();
        for (int s = 128; s > 0; s >>= 1) {
            if (tid < s) sv[tid] = (sv[tid] > sv[tid + s]) ? sv[tid] : sv[tid + s];
            __syncthreads();
        }
        m2 = sv[0]; __syncthreads();
    }
    {
        unsigned long long v = 0ull;
        for (int k = 0; k < nloc; ++k)
            if (loc[k] != m1 && loc[k] != m2) v = (loc[k] > v) ? loc[k] : v;
        sv[tid] = v; __syncthreads();
        for (int s = 128; s > 0; s >>= 1) {
            if (tid < s) sv[tid] = (sv[tid] > sv[tid + s]) ? sv[tid] : sv[tid + s];
            __syncthreads();
        }
        m3 = sv[0];
    }
    if (tid == 0) {
        unsigned c1 = 0xFFFFFFFFu - (unsigned)(m1 & 0xFFFFFFFFull);
        unsigned c2 = (m2 != 0ull) ? (0xFFFFFFFFu - (unsigned)(m2 & 0xFFFFFFFFull)) : c1;
        unsigned c3 = (m3 != 0ull) ? (0xFFFFFFFFu - (unsigned)(m3 & 0xFFFFFFFFull)) : c1;
        scols[0] = c1; scols[1] = c2; scols[2] = c3;
    }
    __syncthreads();

    // ---- phase 2: exact fp32 dots for (model, cand) = (wrp/3, wrp%3) ----
    unsigned col = scols[wrp % 3];
    const float* a = (wrp < 3) ? (x + (size_t)row * HH) : (rx + (size_t)row * HH);
    const float* b = (wrp < 3) ? (w + (size_t)col * HH) : (rw + (size_t)col * HH);
    float s = 0.0f;
    for (int h = lane; h < HH; h += 32) s = fmaf(a[h], b[h], s);
#pragma unroll
    for (int m = 16; m >= 1; m >>= 1) s += __shfl_xor_sync(0xFFFFFFFFu, s, m);
    if (lane == 0) sd[wrp] = s;
    __syncthreads();
    if (tid == 0) {
        int best = 0;
        for (int k = 1; k < 3; ++k) {
            if (sd[k] > sd[best] || (sd[k] == sd[best] && scols[k] < scols[best])) best = k;
        }
        g_pdot[row] = sd[best];
        g_rdot[row] = sd[3 + best];
    }
}

// ---------------- final scalar loss ----------------
__global__ void loss_kernel(const float* __restrict__ adv,
                            const float* __restrict__ oldlp,
                            const int*   __restrict__ mask,
                            float* __restrict__ out) {
    __shared__ float sl[256], sm[256];
    int tid = threadIdx.x;
    float accl = 0.0f, accm = 0.0f;
    for (int r = tid; r < BT; r += 256) {
        int b = r / TT;
        float lse_p = logf(g_sum_pol[r]);
        float lse_r = logf(g_sum_ref[r]);
        float chosen_lp = g_pdot[r] - lse_p;
        float ref_lp    = g_rdot[r] - lse_r;

        float c1 = expf(chosen_lp - oldlp[r]);
        float c2 = fminf(fmaxf(c1, 1.0f - EPS_LO_C), 1.0f + EPS_HI_C);
        float a  = adv[b];
        float ptl = -fminf(c1 * a, c2 * a);

        float delta = ref_lp - chosen_lp;
        float kl = expf(delta) - delta - 1.0f;
        ptl += BETA_C * kl;

        float m = (float)mask[r];
        accl += ptl * m;
        accm += m;
    }
    sl[tid] = accl; sm[tid] = accm;
    __syncthreads();
    for (int s = 128; s > 0; s >>= 1) {
        if (tid < s) { sl[tid] += sl[tid + s]; sm[tid] += sm[tid + s]; }
        __syncthreads();
    }
    if (tid == 0) out[0] = sl[0] / fmaxf(sm[0], 1.0f);
}

// ---------------- launch (fork-join graph; cvt_ref gated AFTER cvt_pol) ----------------
extern "C" void kernel_launch(void* const* d_in, const int* in_sizes, int n_in,
                              void* d_out, int out_size) {
    const float* x    = (const float*)d_in[0];
    const float* w    = (const float*)d_in[1];
    const float* rx   = (const float*)d_in[2];
    const float* rw   = (const float*)d_in[3];
    const float* adv  = (const float*)d_in[4];
    const float* oldl = (const float*)d_in[5];
    const int*   msk  = (const int*)d_in[6];
    float* out = (float*)d_out;

    float *sum_pol, *sum_ref;
    unsigned long long* cand;
    __half *xh, *wh, *rxh, *rwh;
    cudaGetSymbolAddress((void**)&sum_pol, g_sum_pol);
    cudaGetSymbolAddress((void**)&sum_ref, g_sum_ref);
    cudaGetSymbolAddress((void**)&cand,    g_cand);
    cudaGetSymbolAddress((void**)&xh,  g_xh);
    cudaGetSymbolAddress((void**)&wh,  g_wh);
    cudaGetSymbolAddress((void**)&rxh, g_rxh);
    cudaGetSymbolAddress((void**)&rwh, g_rwh);

    cudaFuncSetAttribute(gemm_mma, cudaFuncAttributeMaxDynamicSharedMemorySize, SMEM_DYN);

    cudaStream_t s2;
    cudaStreamCreateWithFlags(&s2, cudaStreamNonBlocking);
    cudaEvent_t eCvtPol, eRefCvt, ePolDone, eGather;
    cudaEventCreateWithFlags(&eCvtPol,  cudaEventDisableTiming);
    cudaEventCreateWithFlags(&eRefCvt,  cudaEventDisableTiming);
    cudaEventCreateWithFlags(&ePolDone, cudaEventDisableTiming);
    cudaEventCreateWithFlags(&eGather,  cudaEventDisableTiming);

    const int ncb = (NPAIR + 255) / 256;
    dim3 grid(BT / BM, VV / BN);   // (16, 500)

    // main: policy convert (+ scratch init) runs ALONE at full DRAM BW
    convert_pair<<<ncb, 256>>>(x, w, xh, wh, 1);
    cudaEventRecord(eCvtPol, 0);                 // fork point for s2

    // main: policy GEMM
    gemm_mma<<<grid, GT, SMEM_DYN>>>(xh, wh, sum_pol, cand, 1);
    cudaEventRecord(ePolDone, 0);

    // s2: ref convert AFTER cvt_pol -> overlaps policy GEMM (DRAM idle there)
    cudaStreamWaitEvent(s2, eCvtPol, 0);
    convert_pair<<<ncb, 256, 0, s2>>>(rx, rw, rxh, rwh, 0);
    cudaEventRecord(eRefCvt, s2);

    // s2: gather_pick needs policy candidates only -> overlaps ref GEMM
    cudaStreamWaitEvent(s2, ePolDone, 0);
    gather_pick<<<BT, 192, 0, s2>>>(x, w, rx, rw);
    cudaEventRecord(eGather, s2);

    // main: ref GEMM (after ref convert), then loss (after gather too)
    cudaStreamWaitEvent(0, eRefCvt, 0);
    gemm_mma<<<grid, GT, SMEM_DYN>>>(rxh, rwh, sum_ref, cand, 0);
    cudaStreamWaitEvent(0, eGather, 0);
    loss_kernel<<<1, 256>>>(adv, oldl, msk, out);

    cudaEventDestroy(eCvtPol);
    cudaEventDestroy(eRefCvt);
    cudaEventDestroy(ePolDone);
    cudaEventDestroy(eGather);
    cudaStreamDestroy(s2);
}